// round 17
// baseline (speedup 1.0000x reference)
#include <cuda_runtime.h>
#include <cuda_fp16.h>
#include <cstdint>

// ============================================================================
// Hyperbolic averaged Hausdorff loss via tensor-core mma.sync (fp16 in/out).
// (build targets plain sm_103: tcgen05 unavailable; legacy HMMA path)
//
// R17 = R16 + occupancy 3 CTAs/SM (launch_bounds 256,3; smem 50KB x3 fits)
//       + finalize folded into the pair kernel tail (last-CTA arcosh+mean).
// Math: acc (f16x2) = -sqdist*invx*invy/2 ; u = 1 - 4*acc (monotone) ->
// row/col mins are packed max(acc); 1 k16 data step + 1 k8 fold step.
// ============================================================================

#define NPTS 16384
#define TILES_PER_SWEEP 8

__device__ int   g_rowmin[NPTS], g_colmin[NPTS];
__device__ int   g_done;
__device__ __half g_B[NPTS * 24];      // 48B per point (24 fp16 cols)

__device__ __forceinline__ uint32_t smem_u32(const void* p) {
    uint32_t a;
    asm("{ .reg .u64 t; cvta.to.shared.u64 t, %1; cvt.u32.u64 %0, t; }"
        : "=r"(a) : "l"(p));
    return a;
}
#define SMEM_SWZ(o) ((o) ^ ((((o) >> 3) & 0x70)))

#define CPASYNC16(dst, src) \
    asm volatile("cp.async.cg.shared.global [%0], [%1], 16;" \
                 :: "r"(dst), "l"(src))
#define CPCOMMIT() asm volatile("cp.async.commit_group;")
#define CPWAIT0()  asm volatile("cp.async.wait_group 0;")

#define LDSM4(r, addr)                                                      \
    asm volatile("ldmatrix.sync.aligned.m8n8.x4.shared.b16 "                \
                 "{%0,%1,%2,%3}, [%4];"                                     \
                 : "=r"((r)[0]), "=r"((r)[1]), "=r"((r)[2]), "=r"((r)[3])   \
                 : "r"(addr))

#define MMA16816H(d, a, b0, b1)                                             \
    asm volatile("mma.sync.aligned.m16n8k16.row.col.f16.f16.f16.f16 "      \
                 "{%0,%1}, {%2,%3,%4,%5}, {%6,%7}, {%0,%1};"                \
                 : "+r"((d)[0]), "+r"((d)[1])                               \
                 : "r"((a)[0]), "r"((a)[1]), "r"((a)[2]), "r"((a)[3]),      \
                   "r"(b0), "r"(b1))

#define MMA16808H(d, a0, a1, b0)                                            \
    asm volatile("mma.sync.aligned.m16n8k8.row.col.f16.f16.f16.f16 "       \
                 "{%0,%1}, {%2,%3}, {%4}, {%0,%1};"                         \
                 : "+r"((d)[0]), "+r"((d)[1])                               \
                 : "r"(a0), "r"(a1), "r"(b0))

#define HMAX2(d, a, b) \
    asm("max.f16x2 %0, %1, %2;" : "=r"(d) : "r"(a), "r"(b))

#define H2_NINF 0xFC00FC00u

// ---------------------------------------------------------------- smem layout
#define SM_A    0                       // 16384   (128 rows x 128B pitch)
#define SM_B    16384                   // 2 x 16384 -> ends 49152
#define SM_ROW  49152                   // 1024B: row staging / final reduce
#define SM_TOT  50176

// --------------------------------------------------------------- split helpers
union HU { __half h; unsigned short u; };
__device__ __forceinline__ unsigned short hfu(float x) {
    HU t; t.h = __float2half_rn(x); return t.u;
}
__device__ __forceinline__ float hff(unsigned short u) {
    HU t; t.u = u; return __half2float(t.h);
}

// Build the 24-col fp16 row (w[12] packed pairs = 48B) for one point.
// A: [xh(16) | Ph,Ph,Pl,Qh,Qh,Ql | 0,0]   P=xn*invx, Q=invx
// B: [yh(16) | Ch,Cl,Ch,Dh,Dl,Dh | 0,0]   C=-invy/2, D=-yn*invy/2
__device__ __forceinline__ void build_row(const float* __restrict__ src,
                                          bool isA, uint32_t* w) {
    float v[16];
    const float4* p = (const float4*)src;
    float4 q0 = p[0], q1 = p[1], q2 = p[2], q3 = p[3];
    v[0]=q0.x; v[1]=q0.y; v[2]=q0.z; v[3]=q0.w;
    v[4]=q1.x; v[5]=q1.y; v[6]=q1.z; v[7]=q1.w;
    v[8]=q2.x; v[9]=q2.y; v[10]=q2.z; v[11]=q2.w;
    v[12]=q3.x; v[13]=q3.y; v[14]=q3.z; v[15]=q3.w;
    float s = 0.f;
#pragma unroll
    for (int d = 0; d < 16; d++) s += v[d] * v[d];
    float inv = 1.0f / (1.0f - s);
#pragma unroll
    for (int d = 0; d < 16; d++) v[d] *= inv;

#pragma unroll
    for (int k = 0; k < 8; k++)
        w[k] = (uint32_t)hfu(v[2*k]) | ((uint32_t)hfu(v[2*k+1]) << 16);

    if (isA) {
        float P = s * inv;
        unsigned short Ph = hfu(P), Pl = hfu(P - hff(Ph));
        unsigned short Qh = hfu(inv), Ql = hfu(inv - hff(Qh));
        w[8]  = (uint32_t)Ph | ((uint32_t)Ph << 16);
        w[9]  = (uint32_t)Pl | ((uint32_t)Qh << 16);
        w[10] = (uint32_t)Qh | ((uint32_t)Ql << 16);
    } else {
        float C = -0.5f * inv;
        unsigned short Ch = hfu(C), Cl = hfu(C - hff(Ch));
        float D = -0.5f * s * inv;
        unsigned short Dh = hfu(D), Dl = hfu(D - hff(Dh));
        w[8]  = (uint32_t)Ch | ((uint32_t)Cl << 16);
        w[9]  = (uint32_t)Ch | ((uint32_t)Dh << 16);
        w[10] = (uint32_t)Dl | ((uint32_t)Dh << 16);
    }
    w[11] = 0u;
}

// ---------------------------------------------------------------- prep kernel
// Y-only: 128 blocks x 128 threads.
__global__ void prep_kernel(const float* __restrict__ Y, int N, int M) {
    int idx = blockIdx.x * 128 + threadIdx.x;
    if (idx == 0) g_done = 0;
    if (idx < N) g_rowmin[idx] = 0x7f800000;
    if (idx < M) {
        g_colmin[idx] = 0x7f800000;
        uint32_t w[12];
        build_row(Y + (size_t)idx * 16, false, w);
        uint4* d4 = (uint4*)(g_B + (size_t)idx * 24);
#pragma unroll
        for (int c = 0; c < 3; c++)
            d4[c] = make_uint4(w[4*c], w[4*c+1], w[4*c+2], w[4*c+3]);
    }
}

// ---------------------------------------------------------------- pair kernel
__global__ void __launch_bounds__(256, 3) pair_mma_kernel(
        const float* __restrict__ X, int N, int M, float* out) {
    extern __shared__ __align__(16) char smem[];
    const uint32_t sb = smem_u32(smem);

    const int tid  = threadIdx.x;
    const int wid  = tid >> 5;
    const int lane = tid & 31;
    const int i0   = blockIdx.y * 128;
    const int jc0  = blockIdx.x * 1024;          // chunk base column

    const int wr = wid & 3;
    const int wc = wid >> 2;
    const int lr = lane & 15;
    const int lc = lane >> 4;

    // B tile = 384 16B chunks (3 per row, gmem pitch 48B)
    const int k0 = tid;
    const int k1 = tid + 256;
    const int r0c = k0 / 3, c0c = k0 - 3 * r0c;
    const int r1c = k1 / 3, c1c = k1 - 3 * r1c;
    const uint32_t bswz0 = SMEM_SWZ(r0c * 128 + c0c * 16);
    const uint32_t bswz1 = SMEM_SWZ(r1c * 128 + c1c * 16);
    const uint32_t bgof0 = (uint32_t)k0 * 16;
    const uint32_t bgof1 = (uint32_t)k1 * 16;

    // ---- prologue: async-copy B tile 0; A tile computed from X in-place
    {
        const char* Bg = (const char*)g_B + (size_t)jc0 * 48;
        CPASYNC16(sb + SM_B + bswz0, Bg + bgof0);
        if (tid < 128) CPASYNC16(sb + SM_B + bswz1, Bg + bgof1);
        CPCOMMIT();
    }
    if (tid < 128) {
        uint32_t w[12];
        build_row(X + (size_t)(i0 + tid) * 16, true, w);
#pragma unroll
        for (int c = 0; c < 3; c++)
            *(uint4*)(smem + SM_A + SMEM_SWZ(tid * 128 + c * 16)) =
                make_uint4(w[4*c], w[4*c+1], w[4*c+2], w[4*c+3]);
    }

    CPWAIT0();
    __syncthreads();

    // ---- A fragments once per sweep: 1 k16 step + 1 k8 fold step
    uint32_t afr[2][4];
#pragma unroll
    for (int mt = 0; mt < 2; mt++) {
        int row = 32*wr + 16*mt + lr;
        LDSM4(afr[mt], sb + SM_A + SMEM_SWZ(row*128 + lc*16));
    }
    uint32_t afr8[4];                    // fold cols 16..23 (byte offset 32)
    LDSM4(afr8, sb + SM_A + SMEM_SWZ((32*wr + lane)*128 + 32));

    // prefetch B tile 1
    {
        const char* Bg = (const char*)g_B + (size_t)(jc0 + 128) * 48;
        uint32_t d = sb + SM_B + 16384;
        CPASYNC16(d + bswz0, Bg + bgof0);
        if (tid < 128) CPASYNC16(d + bswz1, Bg + bgof1);
        CPCOMMIT();
    }

    uint32_t rp[4] = {H2_NINF, H2_NINF, H2_NINF, H2_NINF};  // packed row maxes

    const int b16 = (lane >> 4) & 1;
    const int b8  = (lane >> 3) & 1;
    const int b4  = (lane >> 2) & 1;
    const int ownCol = 8 * (2 * b16 + b8) + 2 * (lane & 3) + b4;

#pragma unroll 1
    for (int t = 0; t < TILES_PER_SWEEP; t++) {
        if (t > 0) {
            CPWAIT0();
            __syncthreads();
            if (t + 1 < TILES_PER_SWEEP) {
                const char* Bg =
                    (const char*)g_B + (size_t)(jc0 + (t + 1) * 128) * 48;
                uint32_t d = sb + SM_B + ((t + 1) & 1) * 16384;
                CPASYNC16(d + bswz0, Bg + bgof0);
                if (tid < 128) CPASYNC16(d + bswz1, Bg + bgof1);
                CPCOMMIT();
            }
        }

        const uint32_t sBb = sb + SM_B + (t & 1) * 16384;
        const int jt = t * 128;

#pragma unroll
        for (int h = 0; h < 2; h++) {
            uint32_t acc[2][4][2];       // [mt][nt][d0,d1] f16x2 pairs
#pragma unroll
            for (int mt = 0; mt < 2; mt++)
#pragma unroll
                for (int nt = 0; nt < 4; nt++) {
                    acc[mt][nt][0] = 0u;
                    acc[mt][nt][1] = 0u;
                }

            // k16 data step (cols 0..15)
            {
                uint32_t b[2][4];
#pragma unroll
                for (int np = 0; np < 2; np++) {
                    int row = 64*wc + 32*h + 16*np + lr;
                    LDSM4(b[np], sBb + SMEM_SWZ(row*128 + lc*16));
                }
#pragma unroll
                for (int mt = 0; mt < 2; mt++)
#pragma unroll
                    for (int nt = 0; nt < 4; nt++) {
                        int np = nt >> 1, od = nt & 1;
                        MMA16816H(acc[mt][nt], afr[mt], b[np][od], b[np][od+2]);
                    }
            }
            // k8 fold step (cols 16..23)
            {
                uint32_t bf8[4];
                LDSM4(bf8, sBb + SMEM_SWZ((64*wc + 32*h + lane)*128 + 32));
#pragma unroll
                for (int mt = 0; mt < 2; mt++)
#pragma unroll
                    for (int nt = 0; nt < 4; nt++)
                        MMA16808H(acc[mt][nt], afr8[2*mt], afr8[2*mt+1], bf8[nt]);
            }

            // ---- epilogue: 1 HMAX2 per 2 elements
            uint32_t vp[4] = {H2_NINF, H2_NINF, H2_NINF, H2_NINF};
#pragma unroll
            for (int mt = 0; mt < 2; mt++)
#pragma unroll
                for (int nt = 0; nt < 4; nt++) {
                    uint32_t* c = acc[mt][nt];
                    HMAX2(rp[2*mt],   rp[2*mt],   c[0]);
                    HMAX2(rp[2*mt+1], rp[2*mt+1], c[1]);
                    uint32_t tm;
                    HMAX2(tm, c[0], c[1]);
                    HMAX2(vp[nt], vp[nt], tm);
                }

            // ---- packed reduce-scatter of col maxes over 8 duplicate lanes
#pragma unroll
            for (int q = 0; q < 2; q++) {
                uint32_t x = b16 ? vp[q] : vp[q + 2];
                uint32_t r = __shfl_xor_sync(0xffffffffu, x, 16);
                if (b16) { HMAX2(vp[q + 2], vp[q + 2], r); }
                else     { HMAX2(vp[q], vp[q], r); }
            }
            uint32_t va = b16 ? vp[2] : vp[0];
            uint32_t vb = b16 ? vp[3] : vp[1];
            {
                uint32_t s2   = b8 ? va : vb;
                uint32_t keep = b8 ? vb : va;
                uint32_t r2 = __shfl_xor_sync(0xffffffffu, s2, 8);
                uint32_t L;
                HMAX2(L, keep, r2);
                uint32_t r3 = __shfl_xor_sync(0xffffffffu, L, 4);
                uint32_t F;
                HMAX2(F, L, r3);
                __half2 hf = *reinterpret_cast<__half2*>(&F);
                float owned = b4 ? __high2float(hf) : __low2float(hf);
                atomicMin(&g_colmin[jc0 + jt + 64*wc + 32*h + ownCol],
                          __float_as_int(fmaxf(-owned, 0.0f)));
            }
        }
    }

    // ---- sweep epilogue: row maxes -> clamped mins
    float* rowp = (float*)(smem + SM_ROW);       // reused staging (2x128)
    // two passes of 128 floats each using the same 1KB buffer
#pragma unroll
    for (int k = 0; k < 4; k++) {
        __half2 h2 = *reinterpret_cast<__half2*>(&rp[k]);
        float v = fmaxf(__low2float(h2), __high2float(h2));
        v = fmaxf(v, __shfl_xor_sync(0xffffffffu, v, 1));
        v = fmaxf(v, __shfl_xor_sync(0xffffffffu, v, 2));
        if ((lane & 3) == 0) {
            int r = 32*wr + 16*(k >> 1) + 8*(k & 1) + (lane >> 2);
            if (wc == 0) rowp[r] = v;
            else         rowp[128 + r] = v;
        }
    }
    __syncthreads();
    if (tid < 128) {
        float rv = fmaxf(rowp[tid], rowp[128 + tid]);
        atomicMin(&g_rowmin[i0 + tid], __float_as_int(fmaxf(-rv, 0.0f)));
    }

    // ---- last CTA: finalize (arcosh + means) -------------------------------
    __threadfence();
    __shared__ int lastFlag;
    if (tid == 0) {
        int t = atomicAdd(&g_done, 1);
        lastFlag = (t == (int)(gridDim.x * gridDim.y) - 1);
    }
    __syncthreads();
    if (lastFlag) {
        float s1 = 0.0f, s2 = 0.0f;
        for (int i = tid; i < N; i += 256) {
            float m = fmaxf(__int_as_float(g_rowmin[i]), 0.0f);
            float u = fmaf(4.0f, m, 1.0f);
            s1 += logf(u + sqrtf(fmaxf(u * u - 1.0f, 0.0f)));
        }
        for (int i = tid; i < M; i += 256) {
            float m = fmaxf(__int_as_float(g_colmin[i]), 0.0f);
            float u = fmaf(4.0f, m, 1.0f);
            s2 += logf(u + sqrtf(fmaxf(u * u - 1.0f, 0.0f)));
        }
        float* red = (float*)(smem + SM_ROW);    // 256 floats fit in 1KB
        red[tid] = s1 * (1.0f / (float)N) + s2 * (1.0f / (float)M);
        __syncthreads();
        for (int s = 128; s > 0; s >>= 1) {
            if (tid < s) red[tid] += red[tid + s];
            __syncthreads();
        }
        if (tid == 0) out[0] = red[0];
    }
}

// ---------------------------------------------------------------- launch
extern "C" void kernel_launch(void* const* d_in, const int* in_sizes, int n_in,
                              void* d_out, int out_size) {
    const float* X = (const float*)d_in[0];
    const float* Y = (const float*)d_in[1];
    int N = in_sizes[0] / 16;
    int M = in_sizes[1] / 16;

    static int configured = 0;
    if (!configured) {
        cudaFuncSetAttribute(pair_mma_kernel,
                             cudaFuncAttributeMaxDynamicSharedMemorySize,
                             SM_TOT);
        configured = 1;
    }

    prep_kernel<<<128, 128>>>(Y, N, M);

    dim3 grid(M / 1024, N / 128);
    pair_mma_kernel<<<grid, 256, SM_TOT>>>(X, N, M, (float*)d_out);
}